// round 2
// baseline (speedup 1.0000x reference)
#include <cuda_runtime.h>
#include <cstdint>

// Problem constants
#define BB 2
#define SS 2048
#define EE 1024
#define HH 16
#define DD 64
#define MM (BB*SS)          // 4096 rows
#define OUT_ELEMS (MM*EE)   // 4194304

// Scratch (device globals: allocation-free rule)
__device__ float g_Q[(size_t)MM * EE];
__device__ float g_K[(size_t)MM * EE];
__device__ float g_V[(size_t)MM * EE];
__device__ float g_C[(size_t)MM * EE];

// ---------------------------------------------------------------------------
// GEMM: C[m,n] = sum_k A[m,k] * W[n,k] + bias[n]
// BM=128, BN=64, BK=16, 256 threads, 8x4 microtile with strided fragments.
// M % 128 == 0, N % 64 == 0, K % 16 == 0 (holds for all 4 uses: 4096/1024/1024)
// ---------------------------------------------------------------------------
__global__ __launch_bounds__(256) void gemm_nt_bias(
    const float* __restrict__ A, const float* __restrict__ W,
    const float* __restrict__ bias, float* __restrict__ C,
    int Mn, int Nn, int Kn)
{
    __shared__ float As[16 * 129];   // [k][m], pad 129
    __shared__ float Bs[16 * 65];    // [k][n], pad 65

    const int tid = threadIdx.x;
    const int tc  = tid & 15;        // 0..15
    const int tr  = tid >> 4;        // 0..15
    const int m0  = blockIdx.y * 128;
    const int n0  = blockIdx.x * 64;

    float acc[8][4];
#pragma unroll
    for (int i = 0; i < 8; i++)
#pragma unroll
        for (int j = 0; j < 4; j++) acc[i][j] = 0.f;

    for (int k0 = 0; k0 < Kn; k0 += 16) {
        // Load A tile 128x16 (512 float4, 2 per thread), store transposed
#pragma unroll
        for (int t = 0; t < 2; t++) {
            int li  = tid + t * 256;
            int row = li >> 2;
            int c4  = (li & 3) << 2;
            float4 v = *(const float4*)(&A[(size_t)(m0 + row) * Kn + k0 + c4]);
            As[(c4 + 0) * 129 + row] = v.x;
            As[(c4 + 1) * 129 + row] = v.y;
            As[(c4 + 2) * 129 + row] = v.z;
            As[(c4 + 3) * 129 + row] = v.w;
        }
        // Load W tile 64x16 (256 float4, 1 per thread), store transposed
        {
            int row = tid >> 2;
            int c4  = (tid & 3) << 2;
            float4 v = *(const float4*)(&W[(size_t)(n0 + row) * Kn + k0 + c4]);
            Bs[(c4 + 0) * 65 + row] = v.x;
            Bs[(c4 + 1) * 65 + row] = v.y;
            Bs[(c4 + 2) * 65 + row] = v.z;
            Bs[(c4 + 3) * 65 + row] = v.w;
        }
        __syncthreads();

#pragma unroll
        for (int k = 0; k < 16; k++) {
            float a[8], bf[4];
#pragma unroll
            for (int i = 0; i < 8; i++) a[i] = As[k * 129 + tr + 16 * i];
#pragma unroll
            for (int j = 0; j < 4; j++) bf[j] = Bs[k * 65 + tc + 16 * j];
#pragma unroll
            for (int i = 0; i < 8; i++)
#pragma unroll
                for (int j = 0; j < 4; j++)
                    acc[i][j] = fmaf(a[i], bf[j], acc[i][j]);
        }
        __syncthreads();
    }

    float bf[4];
#pragma unroll
    for (int j = 0; j < 4; j++) bf[j] = bias[n0 + tc + 16 * j];
#pragma unroll
    for (int i = 0; i < 8; i++) {
        int m = m0 + tr + 16 * i;
#pragma unroll
        for (int j = 0; j < 4; j++) {
            int n = n0 + tc + 16 * j;
            C[(size_t)m * Nn + n] = acc[i][j] + bf[j];
        }
    }
}

// ---------------------------------------------------------------------------
// Attention: per (b, h, 64-query tile). Flash-style, no max-subtraction
// (scores bounded: |gate * q.k / 8| < ~5), deferred normalization.
//   Qs: [d][r] 64x64 unpadded (reads conflict-free; stores once per block)
//   KP: [d][c] then reused as P [c][r], 64x65
//   Vs: [k][d] 64x64 natural (float4 stores, conflict-free reads)
// ---------------------------------------------------------------------------
__global__ __launch_bounds__(256) void attn_kernel(
    const float* __restrict__ Q, const float* __restrict__ K,
    const float* __restrict__ V, const float* __restrict__ z,
    float* __restrict__ Ctx)
{
    extern __shared__ float sm[];
    float* Qs = sm;                 // 64*64
    float* KP = sm + 64 * 64;       // 64*65
    float* Vs = KP + 64 * 65;       // 64*64
    __shared__ float ls[64];

    const int tx  = threadIdx.x;    // 0..15
    const int ty  = threadIdx.y;    // 0..15
    const int tid = ty * 16 + tx;
    const int q0  = blockIdx.x * 64;
    const int h   = blockIdx.y;
    const int b   = blockIdx.z;

    const float gate  = 1.f / (1.f + __expf(-z[h]));
    const float scale = gate * 0.125f;     // gate / sqrt(64)

    const size_t rowBase = (size_t)b * SS;
    const int    colBase = h * 64;

    // Load Q tile [64 rows x 64 d], transposed into Qs[d][r]
#pragma unroll
    for (int t = 0; t < 4; t++) {
        int li  = tid + t * 256;
        int row = li >> 4;
        int c4  = (li & 15) << 2;
        float4 v = *(const float4*)(&Q[(rowBase + q0 + row) * EE + colBase + c4]);
        Qs[(c4 + 0) * 64 + row] = v.x;
        Qs[(c4 + 1) * 64 + row] = v.y;
        Qs[(c4 + 2) * 64 + row] = v.z;
        Qs[(c4 + 3) * 64 + row] = v.w;
    }
    if (tid < 64) ls[tid] = 0.f;

    float o[4][4];
#pragma unroll
    for (int i = 0; i < 4; i++)
#pragma unroll
        for (int j = 0; j < 4; j++) o[i][j] = 0.f;

    for (int kt = 0; kt < SS / 64; kt++) {
        __syncthreads();  // prev GEMM2 done with KP(P)/Vs; Qs/ls ready (iter 0)

        // Load K tile transposed -> KP[d][c]; V tile natural -> Vs[k][d]
#pragma unroll
        for (int t = 0; t < 4; t++) {
            int li  = tid + t * 256;
            int row = li >> 4;
            int c4  = (li & 15) << 2;
            size_t g = (rowBase + kt * 64 + row) * EE + colBase + c4;
            float4 kv = *(const float4*)(&K[g]);
            KP[(c4 + 0) * 65 + row] = kv.x;
            KP[(c4 + 1) * 65 + row] = kv.y;
            KP[(c4 + 2) * 65 + row] = kv.z;
            KP[(c4 + 3) * 65 + row] = kv.w;
            float4 vv = *(const float4*)(&V[g]);
            *(float4*)(&Vs[row * 64 + c4]) = vv;
        }
        __syncthreads();

        // GEMM1: S[r][c] = sum_d Q[r][d] * K[c][d]
        float s_[4][4];
#pragma unroll
        for (int i = 0; i < 4; i++)
#pragma unroll
            for (int j = 0; j < 4; j++) s_[i][j] = 0.f;

#pragma unroll 8
        for (int d = 0; d < 64; d++) {
            float a[4], bb[4];
#pragma unroll
            for (int i = 0; i < 4; i++) a[i]  = Qs[d * 64 + ty + 16 * i];
#pragma unroll
            for (int j = 0; j < 4; j++) bb[j] = KP[d * 65 + tx + 16 * j];
#pragma unroll
            for (int i = 0; i < 4; i++)
#pragma unroll
                for (int j = 0; j < 4; j++)
                    s_[i][j] = fmaf(a[i], bb[j], s_[i][j]);
        }
        __syncthreads();  // all K reads done before P overwrites KP

        // exp + row sums + write P into KP[c][r]
#pragma unroll
        for (int i = 0; i < 4; i++) {
            float rs = 0.f;
#pragma unroll
            for (int j = 0; j < 4; j++) {
                float p = __expf(s_[i][j] * scale);
                s_[i][j] = p;
                rs += p;
            }
            rs += __shfl_xor_sync(0xffffffffu, rs, 8);
            rs += __shfl_xor_sync(0xffffffffu, rs, 4);
            rs += __shfl_xor_sync(0xffffffffu, rs, 2);
            rs += __shfl_xor_sync(0xffffffffu, rs, 1);
            if (tx == 0) ls[ty + 16 * i] += rs;
#pragma unroll
            for (int j = 0; j < 4; j++)
                KP[(tx + 16 * j) * 65 + ty + 16 * i] = s_[i][j];
        }
        __syncthreads();  // P ready

        // GEMM2: O[r][dd] += sum_k P[r][k] * V[k][dd]
#pragma unroll 8
        for (int k = 0; k < 64; k++) {
            float pa[4], vb[4];
#pragma unroll
            for (int i = 0; i < 4; i++) pa[i] = KP[k * 65 + ty + 16 * i];
#pragma unroll
            for (int j = 0; j < 4; j++) vb[j] = Vs[k * 64 + tx + 16 * j];
#pragma unroll
            for (int i = 0; i < 4; i++)
#pragma unroll
                for (int j = 0; j < 4; j++)
                    o[i][j] = fmaf(pa[i], vb[j], o[i][j]);
        }
    }
    __syncthreads();

    // Normalize and write ctx[b, s, h*64+d]
#pragma unroll
    for (int i = 0; i < 4; i++) {
        float inv = 1.f / ls[ty + 16 * i];
        size_t rbase = (rowBase + q0 + ty + 16 * i) * EE + colBase;
#pragma unroll
        for (int j = 0; j < 4; j++)
            Ctx[rbase + tx + 16 * j] = o[i][j] * inv;
    }
}

// Penalty = 0.01 * sum(sigmoid(z))
__global__ void penalty_kernel(const float* __restrict__ z,
                               float* __restrict__ out, int out_size)
{
    if (out_size <= OUT_ELEMS) return;
    float v = 0.f;
    if (threadIdx.x < HH) v = 1.f / (1.f + expf(-z[threadIdx.x]));
#pragma unroll
    for (int off = 16; off > 0; off >>= 1)
        v += __shfl_xor_sync(0xffffffffu, v, off);
    if (threadIdx.x == 0) out[OUT_ELEMS] = v * 0.01f;
}

extern "C" void kernel_launch(void* const* d_in, const int* in_sizes, int n_in,
                              void* d_out, int out_size)
{
    const float* x  = (const float*)d_in[0];
    const float* Wq = (const float*)d_in[1];
    const float* bq = (const float*)d_in[2];
    const float* Wk = (const float*)d_in[3];
    const float* bk = (const float*)d_in[4];
    const float* Wv = (const float*)d_in[5];
    const float* bv = (const float*)d_in[6];
    const float* Wo = (const float*)d_in[7];
    const float* bo = (const float*)d_in[8];
    const float* z  = (const float*)d_in[9];
    float* out = (float*)d_out;

    float *Qp, *Kp, *Vp, *Cp;
    cudaGetSymbolAddress((void**)&Qp, g_Q);
    cudaGetSymbolAddress((void**)&Kp, g_K);
    cudaGetSymbolAddress((void**)&Vp, g_V);
    cudaGetSymbolAddress((void**)&Cp, g_C);

    dim3 ggrid(EE / 64, MM / 128);   // (16, 32) = 512 blocks

    gemm_nt_bias<<<ggrid, 256>>>(x, Wq, bq, Qp, MM, EE, EE);
    gemm_nt_bias<<<ggrid, 256>>>(x, Wk, bk, Kp, MM, EE, EE);
    gemm_nt_bias<<<ggrid, 256>>>(x, Wv, bv, Vp, MM, EE, EE);

    const int smbytes = (64 * 64 + 64 * 65 + 64 * 64) * (int)sizeof(float); // 49664
    cudaFuncSetAttribute(attn_kernel,
                         cudaFuncAttributeMaxDynamicSharedMemorySize, smbytes);
    dim3 agrid(SS / 64, HH, BB);     // (32, 16, 2) = 1024 blocks
    attn_kernel<<<agrid, dim3(16, 16), smbytes>>>(Qp, Kp, Vp, z, Cp);

    gemm_nt_bias<<<ggrid, 256>>>(Cp, Wo, bo, out, MM, EE, EE);

    penalty_kernel<<<1, 32>>>(z, out, out_size);
}

// round 3
// speedup vs baseline: 2.3076x; 2.3076x over previous
#include <cuda_runtime.h>
#include <cuda_bf16.h>
#include <cstdint>

#define BB 2
#define SS 2048
#define EE 1024
#define HH 16
#define DD 64
#define MM (BB*SS)          // 4096
#define OUT_ELEMS (MM*EE)   // 4194304

__device__ float g_Q[(size_t)MM * EE];
__device__ float g_K[(size_t)MM * EE];
__device__ float g_V[(size_t)MM * EE];
__device__ float g_C[(size_t)MM * EE];

// ---------------------------------------------------------------------------
// mma / ldmatrix helpers
// ---------------------------------------------------------------------------
__device__ __forceinline__ void mma16816(float (&d)[4], const uint32_t (&a)[4],
                                         const uint32_t* b) {
    asm volatile(
        "mma.sync.aligned.m16n8k16.row.col.f32.bf16.bf16.f32 "
        "{%0,%1,%2,%3}, {%4,%5,%6,%7}, {%8,%9}, {%0,%1,%2,%3};\n"
        : "+f"(d[0]), "+f"(d[1]), "+f"(d[2]), "+f"(d[3])
        : "r"(a[0]), "r"(a[1]), "r"(a[2]), "r"(a[3]), "r"(b[0]), "r"(b[1]));
}
__device__ __forceinline__ void ldsm4(uint32_t (&r)[4], const __nv_bfloat16* p) {
    uint32_t a = (uint32_t)__cvta_generic_to_shared(p);
    asm volatile("ldmatrix.sync.aligned.m8n8.x4.shared.b16 {%0,%1,%2,%3}, [%4];\n"
                 : "=r"(r[0]), "=r"(r[1]), "=r"(r[2]), "=r"(r[3]) : "r"(a));
}
// split fp32 -> hi/lo bf16 pair stores (2 consecutive elements)
__device__ __forceinline__ void cvt2(float x, float y, __nv_bfloat16* hp,
                                     __nv_bfloat16* lp) {
    __nv_bfloat162 h, l;
    h.x = __float2bfloat16(x); h.y = __float2bfloat16(y);
    l.x = __float2bfloat16(x - __bfloat162float(h.x));
    l.y = __float2bfloat16(y - __bfloat162float(h.y));
    *(__nv_bfloat162*)hp = h;
    *(__nv_bfloat162*)lp = l;
}
__device__ __forceinline__ void cvt1(float x, __nv_bfloat16* hp, __nv_bfloat16* lp) {
    __nv_bfloat16 h = __float2bfloat16(x);
    *hp = h;
    *lp = __float2bfloat16(x - __bfloat162float(h));
}

// ---------------------------------------------------------------------------
// GEMM: C[m,n] = sum_k A[m,k]*W[n,k] + bias[n]   (bf16x3 via mma.sync)
// BM=128, BN=128, BK=32, 256 threads (8 warps: 4 over M x 2 over N)
// ---------------------------------------------------------------------------
#define GST 40   // smem row stride in halves (32 + 8 pad)

__global__ __launch_bounds__(256) void gemm_bf16x3(
    const float* __restrict__ A, const float* __restrict__ W,
    const float* __restrict__ bias, float* __restrict__ C, int Kn, int Nn)
{
    __shared__ __nv_bfloat16 Ah[128 * GST], Al[128 * GST];
    __shared__ __nv_bfloat16 Bh[128 * GST], Bl[128 * GST];

    const int tid  = threadIdx.x;
    const int wid  = tid >> 5, lane = tid & 31;
    const int wm   = wid & 3, wn = wid >> 2;
    const int m0   = blockIdx.y * 128, n0 = blockIdx.x * 128;

    // ldmatrix lane address offsets
    const int arow = (lane & 7) + ((lane >> 3) & 1) * 8;   // A-style
    const int acol = ((lane >> 4) & 1) * 8;
    const int brow = (lane & 7) + ((lane >> 4) & 1) * 8;   // B-style (tile pair)
    const int bcol = ((lane >> 3) & 1) * 8;

    float acc[2][8][4] = {};

    for (int k0 = 0; k0 < Kn; k0 += 32) {
#pragma unroll
        for (int t = 0; t < 4; t++) {
            int idx = tid + t * 256;
            int row = idx >> 3, f4 = (idx & 7) << 2;
            float4 va = *(const float4*)&A[(size_t)(m0 + row) * Kn + k0 + f4];
            cvt2(va.x, va.y, &Ah[row * GST + f4],     &Al[row * GST + f4]);
            cvt2(va.z, va.w, &Ah[row * GST + f4 + 2], &Al[row * GST + f4 + 2]);
            float4 vb = *(const float4*)&W[(size_t)(n0 + row) * Kn + k0 + f4];
            cvt2(vb.x, vb.y, &Bh[row * GST + f4],     &Bl[row * GST + f4]);
            cvt2(vb.z, vb.w, &Bh[row * GST + f4 + 2], &Bl[row * GST + f4 + 2]);
        }
        __syncthreads();

#pragma unroll
        for (int ks = 0; ks < 32; ks += 16) {
            uint32_t ah[2][4], al[2][4];
#pragma unroll
            for (int mt = 0; mt < 2; mt++) {
                int r = (wm * 32 + mt * 16 + arow) * GST + ks + acol;
                ldsm4(ah[mt], &Ah[r]);
                ldsm4(al[mt], &Al[r]);
            }
#pragma unroll
            for (int np = 0; np < 4; np++) {
                int r = (wn * 64 + np * 16 + brow) * GST + ks + bcol;
                uint32_t bh[4], bl[4];
                ldsm4(bh, &Bh[r]);
                ldsm4(bl, &Bl[r]);
#pragma unroll
                for (int mt = 0; mt < 2; mt++) {
                    mma16816(acc[mt][np * 2],     ah[mt], bh);
                    mma16816(acc[mt][np * 2],     ah[mt], bl);
                    mma16816(acc[mt][np * 2],     al[mt], bh);
                    mma16816(acc[mt][np * 2 + 1], ah[mt], bh + 2);
                    mma16816(acc[mt][np * 2 + 1], ah[mt], bl + 2);
                    mma16816(acc[mt][np * 2 + 1], al[mt], bh + 2);
                }
            }
        }
        __syncthreads();
    }

#pragma unroll
    for (int mt = 0; mt < 2; mt++)
#pragma unroll
        for (int nt = 0; nt < 8; nt++) {
            int r = m0 + wm * 32 + mt * 16 + (lane >> 2);
            int c = n0 + wn * 64 + nt * 8 + 2 * (lane & 3);
            float b0 = bias[c], b1 = bias[c + 1];
            *(float2*)&C[(size_t)r * Nn + c] =
                make_float2(acc[mt][nt][0] + b0, acc[mt][nt][1] + b1);
            *(float2*)&C[(size_t)(r + 8) * Nn + c] =
                make_float2(acc[mt][nt][2] + b0, acc[mt][nt][3] + b1);
        }
}

// ---------------------------------------------------------------------------
// Attention (bf16x3 mma): per (b, h, 128-query tile), K-tiles of 64.
// 256 threads (8 warps: 4 over rows x 2 over cols). Deferred normalization.
// smem (halves, row stride 72): Qh/Ql[128], Kh/Kl[64] (as [c][d]),
// Vh/Vl[64] (as [d][c]), Ph/Pl[128]; ls[128] fp32.
// ---------------------------------------------------------------------------
#define AST 72

__global__ __launch_bounds__(256) void attn_bf16x3(
    const float* __restrict__ Q, const float* __restrict__ K,
    const float* __restrict__ V, const float* __restrict__ z,
    float* __restrict__ Ctx)
{
    extern __shared__ __nv_bfloat16 smh[];
    __nv_bfloat16* Qh = smh;
    __nv_bfloat16* Ql = Qh + 128 * AST;
    __nv_bfloat16* Kh = Ql + 128 * AST;
    __nv_bfloat16* Kl = Kh + 64 * AST;
    __nv_bfloat16* Vh = Kl + 64 * AST;
    __nv_bfloat16* Vl = Vh + 64 * AST;
    __nv_bfloat16* Ph = Vl + 64 * AST;
    __nv_bfloat16* Pl = Ph + 128 * AST;
    float* ls = (float*)(Pl + 128 * AST);

    const int tid  = threadIdx.x;
    const int wid  = tid >> 5, lane = tid & 31;
    const int wm   = wid & 3, wn = wid >> 2;
    const int q0   = blockIdx.x * 128;
    const int h    = blockIdx.y;
    const int b    = blockIdx.z;

    const float gate  = 1.f / (1.f + __expf(-z[h]));
    const float scale = gate * 0.125f;
    const size_t rowBase = (size_t)b * SS;
    const int    colBase = h * 64;

    const int arow = (lane & 7) + ((lane >> 3) & 1) * 8;
    const int acol = ((lane >> 4) & 1) * 8;
    const int brow = (lane & 7) + ((lane >> 4) & 1) * 8;
    const int bcol = ((lane >> 3) & 1) * 8;

    // Load + convert Q tile [128 x 64]
#pragma unroll
    for (int t = 0; t < 8; t++) {
        int idx = tid + t * 256;
        int row = idx >> 4, f4 = (idx & 15) << 2;
        float4 v = *(const float4*)&Q[(rowBase + q0 + row) * EE + colBase + f4];
        cvt2(v.x, v.y, &Qh[row * AST + f4],     &Ql[row * AST + f4]);
        cvt2(v.z, v.w, &Qh[row * AST + f4 + 2], &Ql[row * AST + f4 + 2]);
    }
    if (tid < 128) ls[tid] = 0.f;

    float acc_o[2][4][4] = {};

    for (int kt = 0; kt < SS / 64; kt++) {
        __syncthreads();   // prev iter done reading K/V/P smem

        // Load K -> [c][d]; V -> transposed [d][c]
#pragma unroll
        for (int t = 0; t < 4; t++) {
            int idx = tid + t * 256;
            int c = idx >> 4, f4 = (idx & 15) << 2;
            size_t g = (rowBase + kt * 64 + c) * EE + colBase + f4;
            float4 kv = *(const float4*)&K[g];
            cvt2(kv.x, kv.y, &Kh[c * AST + f4],     &Kl[c * AST + f4]);
            cvt2(kv.z, kv.w, &Kh[c * AST + f4 + 2], &Kl[c * AST + f4 + 2]);
            float4 vv = *(const float4*)&V[g];
            cvt1(vv.x, &Vh[(f4 + 0) * AST + c], &Vl[(f4 + 0) * AST + c]);
            cvt1(vv.y, &Vh[(f4 + 1) * AST + c], &Vl[(f4 + 1) * AST + c]);
            cvt1(vv.z, &Vh[(f4 + 2) * AST + c], &Vl[(f4 + 2) * AST + c]);
            cvt1(vv.w, &Vh[(f4 + 3) * AST + c], &Vl[(f4 + 3) * AST + c]);
        }
        __syncthreads();

        // S = Q K^T  (rows wm*32.., cols wn*32..)
        float s[2][4][4] = {};
#pragma unroll
        for (int ks = 0; ks < 4; ks++) {
            uint32_t ah[2][4], al[2][4];
#pragma unroll
            for (int mt = 0; mt < 2; mt++) {
                int r = (wm * 32 + mt * 16 + arow) * AST + ks * 16 + acol;
                ldsm4(ah[mt], &Qh[r]);
                ldsm4(al[mt], &Ql[r]);
            }
#pragma unroll
            for (int np = 0; np < 2; np++) {
                int r = (wn * 32 + np * 16 + brow) * AST + ks * 16 + bcol;
                uint32_t bh[4], bl[4];
                ldsm4(bh, &Kh[r]);
                ldsm4(bl, &Kl[r]);
#pragma unroll
                for (int mt = 0; mt < 2; mt++) {
                    mma16816(s[mt][np * 2],     ah[mt], bh);
                    mma16816(s[mt][np * 2],     ah[mt], bl);
                    mma16816(s[mt][np * 2],     al[mt], bh);
                    mma16816(s[mt][np * 2 + 1], ah[mt], bh + 2);
                    mma16816(s[mt][np * 2 + 1], ah[mt], bl + 2);
                    mma16816(s[mt][np * 2 + 1], al[mt], bh + 2);
                }
            }
        }

        // exp + row sums + store P (hi/lo)
#pragma unroll
        for (int mt = 0; mt < 2; mt++) {
            float rs0 = 0.f, rs1 = 0.f;
            int r0 = wm * 32 + mt * 16 + (lane >> 2);
#pragma unroll
            for (int nt = 0; nt < 4; nt++) {
                float p0 = __expf(s[mt][nt][0] * scale);
                float p1 = __expf(s[mt][nt][1] * scale);
                float p2 = __expf(s[mt][nt][2] * scale);
                float p3 = __expf(s[mt][nt][3] * scale);
                rs0 += p0 + p1;
                rs1 += p2 + p3;
                int c = wn * 32 + nt * 8 + 2 * (lane & 3);
                cvt2(p0, p1, &Ph[r0 * AST + c],       &Pl[r0 * AST + c]);
                cvt2(p2, p3, &Ph[(r0 + 8) * AST + c], &Pl[(r0 + 8) * AST + c]);
            }
            rs0 += __shfl_xor_sync(0xffffffffu, rs0, 1);
            rs0 += __shfl_xor_sync(0xffffffffu, rs0, 2);
            rs1 += __shfl_xor_sync(0xffffffffu, rs1, 1);
            rs1 += __shfl_xor_sync(0xffffffffu, rs1, 2);
            if ((lane & 3) == 0) {
                atomicAdd(&ls[r0], rs0);
                atomicAdd(&ls[r0 + 8], rs1);
            }
        }
        __syncthreads();

        // O += P V   (k over 64 key cols, n over 64 d cols; warp: wn*32..)
#pragma unroll
        for (int ks = 0; ks < 4; ks++) {
            uint32_t ah[2][4], al[2][4];
#pragma unroll
            for (int mt = 0; mt < 2; mt++) {
                int r = (wm * 32 + mt * 16 + arow) * AST + ks * 16 + acol;
                ldsm4(ah[mt], &Ph[r]);
                ldsm4(al[mt], &Pl[r]);
            }
#pragma unroll
            for (int np = 0; np < 2; np++) {
                int r = (wn * 32 + np * 16 + brow) * AST + ks * 16 + bcol;
                uint32_t bh[4], bl[4];
                ldsm4(bh, &Vh[r]);
                ldsm4(bl, &Vl[r]);
#pragma unroll
                for (int mt = 0; mt < 2; mt++) {
                    mma16816(acc_o[mt][np * 2],     ah[mt], bh);
                    mma16816(acc_o[mt][np * 2],     ah[mt], bl);
                    mma16816(acc_o[mt][np * 2],     al[mt], bh);
                    mma16816(acc_o[mt][np * 2 + 1], ah[mt], bh + 2);
                    mma16816(acc_o[mt][np * 2 + 1], ah[mt], bl + 2);
                    mma16816(acc_o[mt][np * 2 + 1], al[mt], bh + 2);
                }
            }
        }
    }

    // Normalize + write ctx
#pragma unroll
    for (int mt = 0; mt < 2; mt++) {
        int r = wm * 32 + mt * 16 + (lane >> 2);
        float inv0 = 1.f / ls[r];
        float inv1 = 1.f / ls[r + 8];
#pragma unroll
        for (int nt = 0; nt < 4; nt++) {
            int c = wn * 32 + nt * 8 + 2 * (lane & 3);
            size_t g0 = (rowBase + q0 + r) * EE + colBase + c;
            size_t g1 = (rowBase + q0 + r + 8) * EE + colBase + c;
            *(float2*)&Ctx[g0] =
                make_float2(acc_o[mt][nt][0] * inv0, acc_o[mt][nt][1] * inv0);
            *(float2*)&Ctx[g1] =
                make_float2(acc_o[mt][nt][2] * inv1, acc_o[mt][nt][3] * inv1);
        }
    }
}

// Penalty = 0.01 * sum(sigmoid(z))
__global__ void penalty_kernel(const float* __restrict__ z,
                               float* __restrict__ out, int out_size)
{
    if (out_size <= OUT_ELEMS) return;
    float v = 0.f;
    if (threadIdx.x < HH) v = 1.f / (1.f + expf(-z[threadIdx.x]));
#pragma unroll
    for (int off = 16; off > 0; off >>= 1)
        v += __shfl_xor_sync(0xffffffffu, v, off);
    if (threadIdx.x == 0) out[OUT_ELEMS] = v * 0.01f;
}

extern "C" void kernel_launch(void* const* d_in, const int* in_sizes, int n_in,
                              void* d_out, int out_size)
{
    const float* x  = (const float*)d_in[0];
    const float* Wq = (const float*)d_in[1];
    const float* bq = (const float*)d_in[2];
    const float* Wk = (const float*)d_in[3];
    const float* bk = (const float*)d_in[4];
    const float* Wv = (const float*)d_in[5];
    const float* bv = (const float*)d_in[6];
    const float* Wo = (const float*)d_in[7];
    const float* bo = (const float*)d_in[8];
    const float* z  = (const float*)d_in[9];
    float* out = (float*)d_out;

    float *Qp, *Kp, *Vp, *Cp;
    cudaGetSymbolAddress((void**)&Qp, g_Q);
    cudaGetSymbolAddress((void**)&Kp, g_K);
    cudaGetSymbolAddress((void**)&Vp, g_V);
    cudaGetSymbolAddress((void**)&Cp, g_C);

    dim3 ggrid(EE / 128, MM / 128);   // (8, 32) = 256 blocks

    gemm_bf16x3<<<ggrid, 256>>>(x, Wq, bq, Qp, EE, EE);
    gemm_bf16x3<<<ggrid, 256>>>(x, Wk, bk, Kp, EE, EE);
    gemm_bf16x3<<<ggrid, 256>>>(x, Wv, bv, Vp, EE, EE);

    const int smbytes = (2 * 128 + 2 * 64 + 2 * 64 + 2 * 128) * AST * 2 + 128 * 4;
    cudaFuncSetAttribute(attn_bf16x3,
                         cudaFuncAttributeMaxDynamicSharedMemorySize, smbytes);
    dim3 agrid(SS / 128, HH, BB);     // (16, 16, 2) = 512 blocks
    attn_bf16x3<<<agrid, 256, smbytes>>>(Qp, Kp, Vp, z, Cp);

    gemm_bf16x3<<<ggrid, 256>>>(Cp, Wo, bo, out, EE, EE);

    penalty_kernel<<<1, 32>>>(z, out, out_size);
}

// round 5
// speedup vs baseline: 4.1947x; 1.8178x over previous
#include <cuda_runtime.h>
#include <cuda_bf16.h>
#include <cuda_fp16.h>
#include <cstdint>

#define BB 2
#define SS 2048
#define EE 1024
#define HH 16
#define MM (BB*SS)          // 4096
#define OUT_ELEMS (MM*EE)   // 4194304
#define NT (SS/64)          // 32 k-tiles

typedef __nv_bfloat16 bf16;
typedef __nv_bfloat162 bf162;

// ---------------- scratch (device globals) ----------------
__device__ bf16 g_xh[(size_t)MM*EE], g_xl[(size_t)MM*EE];
__device__ bf16 g_Wqh[EE*EE], g_Wql[EE*EE];
__device__ bf16 g_Wkh[EE*EE], g_Wkl[EE*EE];
__device__ bf16 g_Wvh[EE*EE], g_Wvl[EE*EE];
__device__ bf16 g_Woh[EE*EE], g_Wol[EE*EE];
__device__ bf16 g_Qh[(size_t)MM*EE], g_Ql[(size_t)MM*EE];
__device__ bf16 g_Kh[(size_t)MM*EE], g_Kl[(size_t)MM*EE];
__device__ __half g_Vt[(size_t)MM*EE];
__device__ bf16 g_Ch[(size_t)MM*EE], g_Cl[(size_t)MM*EE];

// ---------------- asm helpers ----------------
__device__ __forceinline__ void mma_bf(float (&d)[4], const uint32_t (&a)[4],
                                       const uint32_t* b) {
    asm volatile(
        "mma.sync.aligned.m16n8k16.row.col.f32.bf16.bf16.f32 "
        "{%0,%1,%2,%3}, {%4,%5,%6,%7}, {%8,%9}, {%0,%1,%2,%3};\n"
        : "+f"(d[0]), "+f"(d[1]), "+f"(d[2]), "+f"(d[3])
        : "r"(a[0]), "r"(a[1]), "r"(a[2]), "r"(a[3]), "r"(b[0]), "r"(b[1]));
}
__device__ __forceinline__ void mma_f16(float (&d)[4], const uint32_t (&a)[4],
                                        const uint32_t* b) {
    asm volatile(
        "mma.sync.aligned.m16n8k16.row.col.f32.f16.f16.f32 "
        "{%0,%1,%2,%3}, {%4,%5,%6,%7}, {%8,%9}, {%0,%1,%2,%3};\n"
        : "+f"(d[0]), "+f"(d[1]), "+f"(d[2]), "+f"(d[3])
        : "r"(a[0]), "r"(a[1]), "r"(a[2]), "r"(a[3]), "r"(b[0]), "r"(b[1]));
}
__device__ __forceinline__ void ldsm4(uint32_t (&r)[4], const void* p) {
    uint32_t a = (uint32_t)__cvta_generic_to_shared(p);
    asm volatile("ldmatrix.sync.aligned.m8n8.x4.shared.b16 {%0,%1,%2,%3}, [%4];\n"
                 : "=r"(r[0]), "=r"(r[1]), "=r"(r[2]), "=r"(r[3]) : "r"(a));
}
__device__ __forceinline__ void cpa16(void* d, const void* s) {
    uint32_t a = (uint32_t)__cvta_generic_to_shared(d);
    asm volatile("cp.async.cg.shared.global [%0], [%1], 16;\n" :: "r"(a), "l"(s));
}
#define CP_COMMIT() asm volatile("cp.async.commit_group;\n")
#define CP_WAIT(N)  asm volatile("cp.async.wait_group %0;\n" :: "n"(N))

// ---------------- fp32 -> bf16 hi/lo split ----------------
__global__ void split_kernel(const float* __restrict__ in, bf16* __restrict__ hi,
                             bf16* __restrict__ lo, int n4) {
    int i = blockIdx.x * blockDim.x + threadIdx.x;
    if (i >= n4) return;
    float4 v = ((const float4*)in)[i];
    bf162 h0 = __floats2bfloat162_rn(v.x, v.y);
    bf162 h1 = __floats2bfloat162_rn(v.z, v.w);
    bf162 L0, L1;
    L0.x = __float2bfloat16(v.x - __bfloat162float(h0.x));
    L0.y = __float2bfloat16(v.y - __bfloat162float(h0.y));
    L1.x = __float2bfloat16(v.z - __bfloat162float(h1.x));
    L1.y = __float2bfloat16(v.w - __bfloat162float(h1.y));
    ((bf162*)hi)[i*2]   = h0; ((bf162*)hi)[i*2+1] = h1;
    ((bf162*)lo)[i*2]   = L0; ((bf162*)lo)[i*2+1] = L1;
}

// ---------------------------------------------------------------------------
// GEMM: acc[m,n] = sum_k A[m,k]*W[n,k] (bf16x3), epilogue by MODE:
//   MODE 0: +bias -> bf16 hi/lo in [b,h,s,d]      (Q, K)
//   MODE 1: +bias -> fp16 in [b,h,d,s] transposed (V)
//   MODE 2: +bias -> fp32 [m,n]                   (final out)
// BM=128 BN=128 BK=32, 256 thr, 2-stage cp.async.
// ---------------------------------------------------------------------------
#define GST 40   // smem row stride (halves): 32 + 8 pad (16B aligned)

template<int MODE>
__global__ __launch_bounds__(256, 2) void gemm3(
    const bf16* __restrict__ Ah, const bf16* __restrict__ Al,
    const bf16* __restrict__ Bh, const bf16* __restrict__ Bl,
    const float* __restrict__ bias, void* __restrict__ O1, void* __restrict__ O2)
{
    extern __shared__ bf16 sm[];   // 2 stages x 4 arrays x 5120 halves

    const int tid = threadIdx.x, lane = tid & 31, wid = tid >> 5;
    const int wm = wid & 3, wn = wid >> 2;
    const int m0 = blockIdx.y * 128, n0 = blockIdx.x * 128;
    const int arow = (lane & 7) + ((lane >> 3) & 1) * 8, acol = ((lane >> 4) & 1) * 8;
    const int brow = (lane & 7) + ((lane >> 4) & 1) * 8, bcol = ((lane >> 3) & 1) * 8;

    auto issue = [&](int k0, int buf) {
        bf16* base = sm + buf * 4 * 5120;
#pragma unroll
        for (int i = 0; i < 8; i++) {
            int idx = tid + i * 256;          // 0..2047
            int isB = idx >= 1024;
            int rem = idx & 1023;
            int hl  = rem >> 9; rem &= 511;
            int row = rem >> 2, ch = rem & 3;
            const bf16* src;
            bf16* dst;
            if (!isB) {
                src = (hl ? Al : Ah) + (size_t)(m0 + row) * EE + k0 + ch * 8;
                dst = base + hl * 5120 + row * GST + ch * 8;
            } else {
                src = (hl ? Bl : Bh) + (size_t)(n0 + row) * EE + k0 + ch * 8;
                dst = base + (2 + hl) * 5120 + row * GST + ch * 8;
            }
            cpa16(dst, src);
        }
    };

    float acc[2][8][4] = {};
    issue(0, 0);  CP_COMMIT();
    issue(32, 1); CP_COMMIT();

    for (int s = 0; s < EE / 32; s++) {
        CP_WAIT(1);
        __syncthreads();
        bf16* base = sm + (s & 1) * 4 * 5120;
        bf16* sAh = base;            bf16* sAl = base + 5120;
        bf16* sBh = base + 2 * 5120; bf16* sBl = base + 3 * 5120;

#pragma unroll
        for (int ks = 0; ks < 32; ks += 16) {
            uint32_t ah[2][4], al[2][4];
#pragma unroll
            for (int mt = 0; mt < 2; mt++) {
                ldsm4(ah[mt], sAh + (wm * 32 + mt * 16 + arow) * GST + ks + acol);
                ldsm4(al[mt], sAl + (wm * 32 + mt * 16 + arow) * GST + ks + acol);
            }
#pragma unroll
            for (int np = 0; np < 4; np++) {
                uint32_t bhf[4], blf[4];
                ldsm4(bhf, sBh + (wn * 64 + np * 16 + brow) * GST + ks + bcol);
                ldsm4(blf, sBl + (wn * 64 + np * 16 + brow) * GST + ks + bcol);
#pragma unroll
                for (int mt = 0; mt < 2; mt++) {
                    mma_bf(acc[mt][np*2],   ah[mt], bhf);
                    mma_bf(acc[mt][np*2],   ah[mt], blf);
                    mma_bf(acc[mt][np*2],   al[mt], bhf);
                    mma_bf(acc[mt][np*2+1], ah[mt], bhf + 2);
                    mma_bf(acc[mt][np*2+1], ah[mt], blf + 2);
                    mma_bf(acc[mt][np*2+1], al[mt], bhf + 2);
                }
            }
        }
        __syncthreads();
        if (s + 2 < EE / 32) issue((s + 2) * 32, s & 1);
        CP_COMMIT();
    }
    CP_WAIT(0);

#pragma unroll
    for (int mt = 0; mt < 2; mt++) {
        int r = m0 + wm * 32 + mt * 16 + (lane >> 2);
#pragma unroll
        for (int nt = 0; nt < 8; nt++) {
            int c = n0 + wn * 64 + nt * 8 + 2 * (lane & 3);
            float b0 = bias[c], b1 = bias[c + 1];
            float v00 = acc[mt][nt][0] + b0, v01 = acc[mt][nt][1] + b1;
            float v10 = acc[mt][nt][2] + b0, v11 = acc[mt][nt][3] + b1;
            if (MODE == 2) {
                float* O = (float*)O1;
                *(float2*)&O[(size_t)r * EE + c]       = make_float2(v00, v01);
                *(float2*)&O[(size_t)(r + 8) * EE + c] = make_float2(v10, v11);
            } else if (MODE == 0) {
                bf16* Oh = (bf16*)O1; bf16* Ol = (bf16*)O2;
                int b_ = r >> 11, s_ = r & 2047, hh = c >> 6, dd = c & 63;
                size_t o0 = (((size_t)b_ * HH + hh) * SS + s_) * 64 + dd;
                bf162 h2 = __floats2bfloat162_rn(v00, v01), L2;
                L2.x = __float2bfloat16(v00 - __bfloat162float(h2.x));
                L2.y = __float2bfloat16(v01 - __bfloat162float(h2.y));
                *(bf162*)&Oh[o0] = h2; *(bf162*)&Ol[o0] = L2;
                size_t o1 = o0 + (size_t)8 * 64;
                h2 = __floats2bfloat162_rn(v10, v11);
                L2.x = __float2bfloat16(v10 - __bfloat162float(h2.x));
                L2.y = __float2bfloat16(v11 - __bfloat162float(h2.y));
                *(bf162*)&Oh[o1] = h2; *(bf162*)&Ol[o1] = L2;
            } else {  // MODE 1: V fp16 transposed [b,h,d,s]
                __half* V = (__half*)O1;
                int b_ = r >> 11, s_ = r & 2047, hh = c >> 6, dd = c & 63;
                size_t o0 = (((size_t)b_ * HH + hh) * 64 + dd) * SS + s_;
                V[o0]          = __float2half(v00);
                V[o0 + SS]     = __float2half(v01);
                V[o0 + 8]      = __float2half(v10);
                V[o0 + SS + 8] = __float2half(v11);
            }
        }
    }
}

// ---------------------------------------------------------------------------
// Attention: per (b, h, 64-query tile), 128 thr (4 warps x 16 rows).
// QK^T bf16x3 (Q frags register-resident), softmax in regs, P fp16 in regs
// (accumulator->A-frag identity), PV fp16 single MMA. 2-stage cp.async K/V.
// smem halves (stride 72): Qh,Ql[64], Kh,Kl[2][64], V[2][64] = 36864 h = 72KB
// ---------------------------------------------------------------------------
#define AST 72

__global__ __launch_bounds__(128, 3) void attn_pipe(
    const bf16* __restrict__ Qh_, const bf16* __restrict__ Ql_,
    const bf16* __restrict__ Kh_, const bf16* __restrict__ Kl_,
    const __half* __restrict__ Vt_, const float* __restrict__ z,
    bf16* __restrict__ Ch_, bf16* __restrict__ Cl_)
{
    extern __shared__ char smraw[];
    bf16*   sQh = (bf16*)smraw;            // 64*72
    bf16*   sQl = sQh + 64 * AST;
    bf16*   sKh = sQl + 64 * AST;          // 2 x 64*72
    bf16*   sKl = sKh + 2 * 64 * AST;
    __half* sV  = (__half*)(sKl + 2 * 64 * AST);   // 2 x 64*72

    const int tid = threadIdx.x, lane = tid & 31, w = tid >> 5;
    const int q0 = blockIdx.x * 64, h = blockIdx.y, b = blockIdx.z;
    const int bh = b * HH + h;
    const float scale = (1.f / (1.f + __expf(-z[h]))) * 0.125f;

    const size_t qkBase = (size_t)bh * SS * 64;   // [bh][s][d]
    const size_t vBase  = (size_t)bh * 64 * SS;   // [bh][d][s]

    const int arow = (lane & 7) + ((lane >> 3) & 1) * 8, acol = ((lane >> 4) & 1) * 8;
    const int brow = (lane & 7) + ((lane >> 4) & 1) * 8, bcol = ((lane >> 3) & 1) * 8;

    auto issue = [&](int kt, int buf) {
#pragma unroll
        for (int i = 0; i < 12; i++) {
            int idx = tid + i * 128;           // 0..1535
            if (idx < 1024) {                  // K hi/lo
                int hl = idx >> 9, rem = idx & 511, row = rem >> 3, ch = rem & 7;
                const bf16* src = (hl ? Kl_ : Kh_) + qkBase +
                                  (size_t)(kt * 64 + row) * 64 + ch * 8;
                bf16* dst = (hl ? sKl : sKh) + buf * 64 * AST + row * AST + ch * 8;
                cpa16(dst, src);
            } else {                           // V fp16
                int rem = idx - 1024, row = rem >> 3, ch = rem & 7;
                const __half* src = Vt_ + vBase + (size_t)row * SS + kt * 64 + ch * 8;
                __half* dst = sV + buf * 64 * AST + row * AST + ch * 8;
                cpa16(dst, src);
            }
        }
    };

    // group0: Q + stage0 ; group1: stage1
#pragma unroll
    for (int i = 0; i < 8; i++) {
        int idx = tid + i * 128;
        int hl = idx >> 9, rem = idx & 511, row = rem >> 3, ch = rem & 7;
        const bf16* src = (hl ? Ql_ : Qh_) + qkBase + (size_t)(q0 + row) * 64 + ch * 8;
        bf16* dst = (hl ? sQl : sQh) + row * AST + ch * 8;
        cpa16(dst, src);
    }
    issue(0, 0); CP_COMMIT();
    issue(1, 1); CP_COMMIT();

    CP_WAIT(1);
    __syncthreads();

    // Q fragments -> registers (whole kernel lifetime)
    uint32_t qh[4][4], ql[4][4];
#pragma unroll
    for (int kc = 0; kc < 4; kc++) {
        ldsm4(qh[kc], sQh + (w * 16 + arow) * AST + kc * 16 + acol);
        ldsm4(ql[kc], sQl + (w * 16 + arow) * AST + kc * 16 + acol);
    }

    float o[8][4] = {};
    float l0 = 0.f, l1 = 0.f;

    for (int kt = 0; kt < NT; kt++) {
        int buf = kt & 1;
        if (kt) { CP_WAIT(1); __syncthreads(); }

        const bf16*   kh0 = sKh + buf * 64 * AST;
        const bf16*   kl0 = sKl + buf * 64 * AST;
        const __half* v0  = sV  + buf * 64 * AST;

        // S = Q K^T  (16 rows x 64 cols per warp)
        float s[8][4] = {};
#pragma unroll
        for (int nc = 0; nc < 4; nc++) {
#pragma unroll
            for (int kc = 0; kc < 4; kc++) {
                uint32_t bhf[4], blf[4];
                ldsm4(bhf, kh0 + (nc * 16 + brow) * AST + kc * 16 + bcol);
                ldsm4(blf, kl0 + (nc * 16 + brow) * AST + kc * 16 + bcol);
                mma_bf(s[nc*2],   qh[kc], bhf);
                mma_bf(s[nc*2],   qh[kc], blf);
                mma_bf(s[nc*2],   ql[kc], bhf);
                mma_bf(s[nc*2+1], qh[kc], bhf + 2);
                mma_bf(s[nc*2+1], qh[kc], blf + 2);
                mma_bf(s[nc*2+1], ql[kc], bhf + 2);
            }
        }

        // exp, row-sum accumulate, pack P as fp16 A-frags (C-frag == A-frag map)
        uint32_t p[4][4];
#pragma unroll
        for (int t = 0; t < 8; t++) {
            float e0 = __expf(s[t][0] * scale), e1 = __expf(s[t][1] * scale);
            float e2 = __expf(s[t][2] * scale), e3 = __expf(s[t][3] * scale);
            l0 += e0 + e1;  l1 += e2 + e3;
            int kc = t >> 1, hf = t & 1;
            __half2 p01 = __floats2half2_rn(e0, e1);
            __half2 p23 = __floats2half2_rn(e2, e3);
            p[kc][hf*2]   = *(uint32_t*)&p01;
            p[kc][hf*2+1] = *(uint32_t*)&p23;
        }

        // O += P V
#pragma unroll
        for (int nd = 0; nd < 4; nd++) {
#pragma unroll
            for (int kc = 0; kc < 4; kc++) {
                uint32_t vb[4];
                ldsm4(vb, v0 + (nd * 16 + brow) * AST + kc * 16 + bcol);
                mma_f16(o[nd*2],   p[kc], vb);
                mma_f16(o[nd*2+1], p[kc], vb + 2);
            }
        }

        __syncthreads();
        if (kt + 2 < NT) issue(kt + 2, buf);
        CP_COMMIT();
    }
    CP_WAIT(0);

    // finalize row sums (quad reduce) and write ctx hi/lo bf16
    l0 += __shfl_xor_sync(0xffffffffu, l0, 1);
    l0 += __shfl_xor_sync(0xffffffffu, l0, 2);
    l1 += __shfl_xor_sync(0xffffffffu, l1, 1);
    l1 += __shfl_xor_sync(0xffffffffu, l1, 2);
    float inv0 = 1.f / l0, inv1 = 1.f / l1;

    int r0 = q0 + w * 16 + (lane >> 2);
#pragma unroll
    for (int t = 0; t < 8; t++) {
        int c = h * 64 + t * 8 + 2 * (lane & 3);
        size_t g0 = ((size_t)b * SS + r0) * EE + c;
        size_t g1 = ((size_t)b * SS + r0 + 8) * EE + c;
        float v00 = o[t][0] * inv0, v01 = o[t][1] * inv0;
        float v10 = o[t][2] * inv1, v11 = o[t][3] * inv1;
        bf162 h2 = __floats2bfloat162_rn(v00, v01), L2;
        L2.x = __float2bfloat16(v00 - __bfloat162float(h2.x));
        L2.y = __float2bfloat16(v01 - __bfloat162float(h2.y));
        *(bf162*)&Ch_[g0] = h2; *(bf162*)&Cl_[g0] = L2;
        h2 = __floats2bfloat162_rn(v10, v11);
        L2.x = __float2bfloat16(v10 - __bfloat162float(h2.x));
        L2.y = __float2bfloat16(v11 - __bfloat162float(h2.y));
        *(bf162*)&Ch_[g1] = h2; *(bf162*)&Cl_[g1] = L2;
    }
}

// Penalty = 0.01 * sum(sigmoid(z))
__global__ void penalty_kernel(const float* __restrict__ z,
                               float* __restrict__ out, int out_size)
{
    if (out_size <= OUT_ELEMS) return;
    float v = 0.f;
    if (threadIdx.x < HH) v = 1.f / (1.f + expf(-z[threadIdx.x]));
#pragma unroll
    for (int off = 16; off > 0; off >>= 1)
        v += __shfl_xor_sync(0xffffffffu, v, off);
    if (threadIdx.x == 0) out[OUT_ELEMS] = v * 0.01f;
}

extern "C" void kernel_launch(void* const* d_in, const int* in_sizes, int n_in,
                              void* d_out, int out_size)
{
    const float* x  = (const float*)d_in[0];
    const float* Wq = (const float*)d_in[1];
    const float* bq = (const float*)d_in[2];
    const float* Wk = (const float*)d_in[3];
    const float* bk = (const float*)d_in[4];
    const float* Wv = (const float*)d_in[5];
    const float* bv = (const float*)d_in[6];
    const float* Wo = (const float*)d_in[7];
    const float* bo = (const float*)d_in[8];
    const float* z  = (const float*)d_in[9];
    float* out = (float*)d_out;

    bf16 *xh, *xl, *Wqh, *Wql, *Wkh, *Wkl, *Wvh, *Wvl, *Woh, *Wol;
    bf16 *Qh, *Ql, *Kh, *Kl, *Ch, *Cl;
    __half* Vt;
    cudaGetSymbolAddress((void**)&xh, g_xh);   cudaGetSymbolAddress((void**)&xl, g_xl);
    cudaGetSymbolAddress((void**)&Wqh, g_Wqh); cudaGetSymbolAddress((void**)&Wql, g_Wql);
    cudaGetSymbolAddress((void**)&Wkh, g_Wkh); cudaGetSymbolAddress((void**)&Wkl, g_Wkl);
    cudaGetSymbolAddress((void**)&Wvh, g_Wvh); cudaGetSymbolAddress((void**)&Wvl, g_Wvl);
    cudaGetSymbolAddress((void**)&Woh, g_Woh); cudaGetSymbolAddress((void**)&Wol, g_Wol);
    cudaGetSymbolAddress((void**)&Qh, g_Qh);   cudaGetSymbolAddress((void**)&Ql, g_Ql);
    cudaGetSymbolAddress((void**)&Kh, g_Kh);   cudaGetSymbolAddress((void**)&Kl, g_Kl);
    cudaGetSymbolAddress((void**)&Vt, g_Vt);
    cudaGetSymbolAddress((void**)&Ch, g_Ch);   cudaGetSymbolAddress((void**)&Cl, g_Cl);

    // ---- prep: split fp32 -> bf16 hi/lo
    split_kernel<<<(MM*EE/4 + 255)/256, 256>>>(x,  xh,  xl,  MM*EE/4);
    split_kernel<<<(EE*EE/4 + 255)/256, 256>>>(Wq, Wqh, Wql, EE*EE/4);
    split_kernel<<<(EE*EE/4 + 255)/256, 256>>>(Wk, Wkh, Wkl, EE*EE/4);
    split_kernel<<<(EE*EE/4 + 255)/256, 256>>>(Wv, Wvh, Wvl, EE*EE/4);
    split_kernel<<<(EE*EE/4 + 255)/256, 256>>>(Wo, Woh, Wol, EE*EE/4);

    const int GSM = 2 * 4 * 5120 * 2;     // 81920 B
    cudaFuncSetAttribute(gemm3<0>, cudaFuncAttributeMaxDynamicSharedMemorySize, GSM);
    cudaFuncSetAttribute(gemm3<1>, cudaFuncAttributeMaxDynamicSharedMemorySize, GSM);
    cudaFuncSetAttribute(gemm3<2>, cudaFuncAttributeMaxDynamicSharedMemorySize, GSM);

    dim3 ggrid(EE / 128, MM / 128);       // (8, 32)
    gemm3<0><<<ggrid, 256, GSM>>>(xh, xl, Wqh, Wql, bq, Qh, Ql);
    gemm3<0><<<ggrid, 256, GSM>>>(xh, xl, Wkh, Wkl, bk, Kh, Kl);
    gemm3<1><<<ggrid, 256, GSM>>>(xh, xl, Wvh, Wvl, bv, Vt, nullptr);

    const int ASM = 8 * 64 * AST * 2;     // 73728 B
    cudaFuncSetAttribute(attn_pipe, cudaFuncAttributeMaxDynamicSharedMemorySize, ASM);
    dim3 agrid(SS / 64, HH, BB);          // (32, 16, 2)
    attn_pipe<<<agrid, 128, ASM>>>(Qh, Ql, Kh, Kl, Vt, z, Ch, Cl);

    gemm3<2><<<ggrid, 256, GSM>>>(Ch, Cl, Woh, Wol, bo, out, nullptr);

    penalty_kernel<<<1, 32>>>(z, out, out_size);
}

// round 7
// speedup vs baseline: 6.0347x; 1.4387x over previous
#include <cuda_runtime.h>
#include <cuda_bf16.h>
#include <cuda_fp16.h>
#include <cstdint>

#define BB 2
#define SS 2048
#define EE 1024
#define HH 16
#define MM (BB*SS)          // 4096
#define OUT_ELEMS (MM*EE)   // 4194304
#define NT (SS/64)          // 32 k-tiles

typedef __nv_bfloat16 bf16;
typedef __nv_bfloat162 bf162;

// ---------------- scratch (device globals) ----------------
__device__ bf16   g_xh[(size_t)MM*EE], g_xl[(size_t)MM*EE];
__device__ __half g_x16[(size_t)MM*EE];
__device__ __half g_Wq16[EE*EE], g_Wk16[EE*EE];
__device__ bf16   g_Wvh[EE*EE], g_Wvl[EE*EE];
__device__ bf16   g_Woh[EE*EE], g_Wol[EE*EE];
__device__ __half g_Q16[(size_t)MM*EE];
__device__ __half g_K16[(size_t)MM*EE];
__device__ __half g_Vt[(size_t)MM*EE];
__device__ bf16   g_Ch[(size_t)MM*EE], g_Cl[(size_t)MM*EE];

// ---------------- asm helpers ----------------
__device__ __forceinline__ void mma_bf(float (&d)[4], const uint32_t (&a)[4],
                                       const uint32_t* b) {
    asm volatile(
        "mma.sync.aligned.m16n8k16.row.col.f32.bf16.bf16.f32 "
        "{%0,%1,%2,%3}, {%4,%5,%6,%7}, {%8,%9}, {%0,%1,%2,%3};\n"
        : "+f"(d[0]), "+f"(d[1]), "+f"(d[2]), "+f"(d[3])
        : "r"(a[0]), "r"(a[1]), "r"(a[2]), "r"(a[3]), "r"(b[0]), "r"(b[1]));
}
__device__ __forceinline__ void mma_f16(float (&d)[4], const uint32_t (&a)[4],
                                        const uint32_t* b) {
    asm volatile(
        "mma.sync.aligned.m16n8k16.row.col.f32.f16.f16.f32 "
        "{%0,%1,%2,%3}, {%4,%5,%6,%7}, {%8,%9}, {%0,%1,%2,%3};\n"
        : "+f"(d[0]), "+f"(d[1]), "+f"(d[2]), "+f"(d[3])
        : "r"(a[0]), "r"(a[1]), "r"(a[2]), "r"(a[3]), "r"(b[0]), "r"(b[1]));
}
__device__ __forceinline__ void ldsm4(uint32_t (&r)[4], const void* p) {
    uint32_t a = (uint32_t)__cvta_generic_to_shared(p);
    asm volatile("ldmatrix.sync.aligned.m8n8.x4.shared.b16 {%0,%1,%2,%3}, [%4];\n"
                 : "=r"(r[0]), "=r"(r[1]), "=r"(r[2]), "=r"(r[3]) : "r"(a));
}
__device__ __forceinline__ void cpa16(void* d, const void* s) {
    uint32_t a = (uint32_t)__cvta_generic_to_shared(d);
    asm volatile("cp.async.cg.shared.global [%0], [%1], 16;\n" :: "r"(a), "l"(s));
}
#define CP_COMMIT() asm volatile("cp.async.commit_group;\n")
#define CP_WAIT(N)  asm volatile("cp.async.wait_group %0;\n" :: "n"(N))

// ---------------- prep kernels ----------------
// x: fp32 -> bf16 hi/lo + fp16
__global__ void split_x_kernel(const float* __restrict__ in, bf16* __restrict__ hi,
                               bf16* __restrict__ lo, __half* __restrict__ h16,
                               int n4) {
    int i = blockIdx.x * blockDim.x + threadIdx.x;
    if (i >= n4) return;
    float4 v = ((const float4*)in)[i];
    bf162 h0 = __floats2bfloat162_rn(v.x, v.y);
    bf162 h1 = __floats2bfloat162_rn(v.z, v.w);
    bf162 L0, L1;
    L0.x = __float2bfloat16(v.x - __bfloat162float(h0.x));
    L0.y = __float2bfloat16(v.y - __bfloat162float(h0.y));
    L1.x = __float2bfloat16(v.z - __bfloat162float(h1.x));
    L1.y = __float2bfloat16(v.w - __bfloat162float(h1.y));
    ((bf162*)hi)[i*2]   = h0; ((bf162*)hi)[i*2+1] = h1;
    ((bf162*)lo)[i*2]   = L0; ((bf162*)lo)[i*2+1] = L1;
    ((__half2*)h16)[i*2]   = __floats2half2_rn(v.x, v.y);
    ((__half2*)h16)[i*2+1] = __floats2half2_rn(v.z, v.w);
}
// fp32 -> bf16 hi/lo (Wv, Wo)
__global__ void split_kernel(const float* __restrict__ in, bf16* __restrict__ hi,
                             bf16* __restrict__ lo, int n4) {
    int i = blockIdx.x * blockDim.x + threadIdx.x;
    if (i >= n4) return;
    float4 v = ((const float4*)in)[i];
    bf162 h0 = __floats2bfloat162_rn(v.x, v.y);
    bf162 h1 = __floats2bfloat162_rn(v.z, v.w);
    bf162 L0, L1;
    L0.x = __float2bfloat16(v.x - __bfloat162float(h0.x));
    L0.y = __float2bfloat16(v.y - __bfloat162float(h0.y));
    L1.x = __float2bfloat16(v.z - __bfloat162float(h1.x));
    L1.y = __float2bfloat16(v.w - __bfloat162float(h1.y));
    ((bf162*)hi)[i*2]   = h0; ((bf162*)hi)[i*2+1] = h1;
    ((bf162*)lo)[i*2]   = L0; ((bf162*)lo)[i*2+1] = L1;
}
// fp32 -> fp16 (Wq, Wk)
__global__ void cvt16_kernel(const float* __restrict__ in, __half* __restrict__ o,
                             int n4) {
    int i = blockIdx.x * blockDim.x + threadIdx.x;
    if (i >= n4) return;
    float4 v = ((const float4*)in)[i];
    ((__half2*)o)[i*2]   = __floats2half2_rn(v.x, v.y);
    ((__half2*)o)[i*2+1] = __floats2half2_rn(v.z, v.w);
}

#define GST 40   // smem row stride (halves): 32 + 8 pad

// ---------------------------------------------------------------------------
// fp16-single GEMM (Q, K projections): C = x @ W^T + b -> fp16 [b,h,s,d]
// BM=128 BN=128 BK=32, 256 thr, 2-stage cp.async.
// ---------------------------------------------------------------------------
__global__ __launch_bounds__(256, 2) void gemm_f16(
    const __half* __restrict__ A, const __half* __restrict__ B,
    const float* __restrict__ bias, __half* __restrict__ O)
{
    extern __shared__ __half smh[];   // 2 stages x 2 arrays x 5120 halves

    const int tid = threadIdx.x, lane = tid & 31, wid = tid >> 5;
    const int wm = wid & 3, wn = wid >> 2;
    const int m0 = blockIdx.y * 128, n0 = blockIdx.x * 128;
    const int arow = (lane & 7) + ((lane >> 3) & 1) * 8, acol = ((lane >> 4) & 1) * 8;
    const int brow = (lane & 7) + ((lane >> 4) & 1) * 8, bcol = ((lane >> 3) & 1) * 8;

    auto issue = [&](int k0, int buf) {
        __half* base = smh + buf * 2 * 5120;
#pragma unroll
        for (int i = 0; i < 4; i++) {
            int idx = tid + i * 256;          // 0..1023
            int isB = idx >= 512;
            int rem = idx & 511;
            int row = rem >> 2, ch = rem & 3;
            const __half* src = (isB ? B + (size_t)(n0 + row) * EE
                                     : A + (size_t)(m0 + row) * EE) + k0 + ch * 8;
            __half* dst = base + isB * 5120 + row * GST + ch * 8;
            cpa16(dst, src);
        }
    };

    float acc[2][8][4] = {};
    issue(0, 0);  CP_COMMIT();
    issue(32, 1); CP_COMMIT();

    for (int s = 0; s < EE / 32; s++) {
        CP_WAIT(1);
        __syncthreads();
        __half* sA = smh + (s & 1) * 2 * 5120;
        __half* sB = sA + 5120;

#pragma unroll
        for (int ks = 0; ks < 32; ks += 16) {
            uint32_t a[2][4];
#pragma unroll
            for (int mt = 0; mt < 2; mt++)
                ldsm4(a[mt], sA + (wm * 32 + mt * 16 + arow) * GST + ks + acol);
#pragma unroll
            for (int np = 0; np < 4; np++) {
                uint32_t bf[4];
                ldsm4(bf, sB + (wn * 64 + np * 16 + brow) * GST + ks + bcol);
#pragma unroll
                for (int mt = 0; mt < 2; mt++) {
                    mma_f16(acc[mt][np*2],   a[mt], bf);
                    mma_f16(acc[mt][np*2+1], a[mt], bf + 2);
                }
            }
        }
        __syncthreads();
        if (s + 2 < EE / 32) issue((s + 2) * 32, s & 1);
        CP_COMMIT();
    }
    CP_WAIT(0);

#pragma unroll
    for (int mt = 0; mt < 2; mt++) {
        int r = m0 + wm * 32 + mt * 16 + (lane >> 2);
#pragma unroll
        for (int nt = 0; nt < 8; nt++) {
            int c = n0 + wn * 64 + nt * 8 + 2 * (lane & 3);
            float b0 = bias[c], b1 = bias[c + 1];
            int b_ = r >> 11, s_ = r & 2047, hh = c >> 6, dd = c & 63;
            size_t o0 = (((size_t)b_ * HH + hh) * SS + s_) * 64 + dd;
            *(__half2*)&O[o0] = __floats2half2_rn(acc[mt][nt][0] + b0,
                                                  acc[mt][nt][1] + b1);
            size_t o1 = o0 + (size_t)8 * 64;
            *(__half2*)&O[o1] = __floats2half2_rn(acc[mt][nt][2] + b0,
                                                  acc[mt][nt][3] + b1);
        }
    }
}

// ---------------------------------------------------------------------------
// bf16x3 GEMM (V, O projections), from R5 (validated):
//   MODE 1: +bias -> fp16 in [b,h,d,s] transposed (V)
//   MODE 2: +bias -> fp32 [m,n]                   (final out)
// ---------------------------------------------------------------------------
template<int MODE>
__global__ __launch_bounds__(256, 2) void gemm3(
    const bf16* __restrict__ Ah, const bf16* __restrict__ Al,
    const bf16* __restrict__ Bh, const bf16* __restrict__ Bl,
    const float* __restrict__ bias, void* __restrict__ O1)
{
    extern __shared__ bf16 sm[];   // 2 stages x 4 arrays x 5120 halves

    const int tid = threadIdx.x, lane = tid & 31, wid = tid >> 5;
    const int wm = wid & 3, wn = wid >> 2;
    const int m0 = blockIdx.y * 128, n0 = blockIdx.x * 128;
    const int arow = (lane & 7) + ((lane >> 3) & 1) * 8, acol = ((lane >> 4) & 1) * 8;
    const int brow = (lane & 7) + ((lane >> 4) & 1) * 8, bcol = ((lane >> 3) & 1) * 8;

    auto issue = [&](int k0, int buf) {
        bf16* base = sm + buf * 4 * 5120;
#pragma unroll
        for (int i = 0; i < 8; i++) {
            int idx = tid + i * 256;          // 0..2047
            int isB = idx >= 1024;
            int rem = idx & 1023;
            int hl  = rem >> 9; rem &= 511;
            int row = rem >> 2, ch = rem & 3;
            const bf16* src;
            bf16* dst;
            if (!isB) {
                src = (hl ? Al : Ah) + (size_t)(m0 + row) * EE + k0 + ch * 8;
                dst = base + hl * 5120 + row * GST + ch * 8;
            } else {
                src = (hl ? Bl : Bh) + (size_t)(n0 + row) * EE + k0 + ch * 8;
                dst = base + (2 + hl) * 5120 + row * GST + ch * 8;
            }
            cpa16(dst, src);
        }
    };

    float acc[2][8][4] = {};
    issue(0, 0);  CP_COMMIT();
    issue(32, 1); CP_COMMIT();

    for (int s = 0; s < EE / 32; s++) {
        CP_WAIT(1);
        __syncthreads();
        bf16* base = sm + (s & 1) * 4 * 5120;
        bf16* sAh = base;            bf16* sAl = base + 5120;
        bf16* sBh = base + 2 * 5120; bf16* sBl = base + 3 * 5120;

#pragma unroll
        for (int ks = 0; ks < 32; ks += 16) {
            uint32_t ah[2][4], al[2][4];
#pragma unroll
            for (int mt = 0; mt < 2; mt++) {
                ldsm4(ah[mt], sAh + (wm * 32 + mt * 16 + arow) * GST + ks + acol);
                ldsm4(al[mt], sAl + (wm * 32 + mt * 16 + arow) * GST + ks + acol);
            }
#pragma unroll
            for (int np = 0; np < 4; np++) {
                uint32_t bhf[4], blf[4];
                ldsm4(bhf, sBh + (wn * 64 + np * 16 + brow) * GST + ks + bcol);
                ldsm4(blf, sBl + (wn * 64 + np * 16 + brow) * GST + ks + bcol);
#pragma unroll
                for (int mt = 0; mt < 2; mt++) {
                    mma_bf(acc[mt][np*2],   ah[mt], bhf);
                    mma_bf(acc[mt][np*2],   ah[mt], blf);
                    mma_bf(acc[mt][np*2],   al[mt], bhf);
                    mma_bf(acc[mt][np*2+1], ah[mt], bhf + 2);
                    mma_bf(acc[mt][np*2+1], ah[mt], blf + 2);
                    mma_bf(acc[mt][np*2+1], al[mt], bhf + 2);
                }
            }
        }
        __syncthreads();
        if (s + 2 < EE / 32) issue((s + 2) * 32, s & 1);
        CP_COMMIT();
    }
    CP_WAIT(0);

#pragma unroll
    for (int mt = 0; mt < 2; mt++) {
        int r = m0 + wm * 32 + mt * 16 + (lane >> 2);
#pragma unroll
        for (int nt = 0; nt < 8; nt++) {
            int c = n0 + wn * 64 + nt * 8 + 2 * (lane & 3);
            float b0 = bias[c], b1 = bias[c + 1];
            float v00 = acc[mt][nt][0] + b0, v01 = acc[mt][nt][1] + b1;
            float v10 = acc[mt][nt][2] + b0, v11 = acc[mt][nt][3] + b1;
            if (MODE == 2) {
                float* O = (float*)O1;
                *(float2*)&O[(size_t)r * EE + c]       = make_float2(v00, v01);
                *(float2*)&O[(size_t)(r + 8) * EE + c] = make_float2(v10, v11);
            } else {  // MODE 1: V fp16 transposed [b,h,d,s]
                __half* V = (__half*)O1;
                int b_ = r >> 11, s_ = r & 2047, hh = c >> 6, dd = c & 63;
                size_t o0 = (((size_t)b_ * HH + hh) * 64 + dd) * SS + s_;
                V[o0]          = __float2half(v00);
                V[o0 + SS]     = __float2half(v01);
                V[o0 + 8]      = __float2half(v10);
                V[o0 + SS + 8] = __float2half(v11);
            }
        }
    }
}

// ---------------------------------------------------------------------------
// Attention: fp16 QK^T single-MMA + fp16 PV. Per (b,h,64-query tile), 128 thr.
// smem fp16 (stride 72): Q[64], K[2][64], V[2][64] = 23040 halves = 46080 B.
// ---------------------------------------------------------------------------
#define AST 72

__global__ __launch_bounds__(128, 4) void attn_pipe(
    const __half* __restrict__ Q16, const __half* __restrict__ K16,
    const __half* __restrict__ Vt_, const float* __restrict__ z,
    bf16* __restrict__ Ch_, bf16* __restrict__ Cl_)
{
    extern __shared__ __half smf[];
    __half* sQ = smf;                       // 64*72
    __half* sK = sQ + 64 * AST;             // 2 x 64*72
    __half* sV = sK + 2 * 64 * AST;         // 2 x 64*72

    const int tid = threadIdx.x, lane = tid & 31, w = tid >> 5;
    const int q0 = blockIdx.x * 64, h = blockIdx.y, b = blockIdx.z;
    const int bh = b * HH + h;
    const float scale = (1.f / (1.f + __expf(-z[h]))) * 0.125f;

    const size_t qkBase = (size_t)bh * SS * 64;   // [bh][s][d]
    const size_t vBase  = (size_t)bh * 64 * SS;   // [bh][d][s]

    const int arow = (lane & 7) + ((lane >> 3) & 1) * 8, acol = ((lane >> 4) & 1) * 8;
    const int brow = (lane & 7) + ((lane >> 4) & 1) * 8, bcol = ((lane >> 3) & 1) * 8;

    auto issue = [&](int kt, int buf) {
#pragma unroll
        for (int i = 0; i < 8; i++) {
            int idx = tid + i * 128;           // 0..1023
            if (idx < 512) {                   // K tile
                int row = idx >> 3, ch = idx & 7;
                const __half* src = K16 + qkBase +
                                    (size_t)(kt * 64 + row) * 64 + ch * 8;
                cpa16(sK + buf * 64 * AST + row * AST + ch * 8, src);
            } else {                           // V tile
                int rem = idx - 512, row = rem >> 3, ch = rem & 7;
                const __half* src = Vt_ + vBase + (size_t)row * SS + kt * 64 + ch * 8;
                cpa16(sV + buf * 64 * AST + row * AST + ch * 8, src);
            }
        }
    };

    // Q tile (with stage-0 group)
#pragma unroll
    for (int i = 0; i < 4; i++) {
        int idx = tid + i * 128;               // 0..511
        int row = idx >> 3, ch = idx & 7;
        cpa16(sQ + row * AST + ch * 8,
              Q16 + qkBase + (size_t)(q0 + row) * 64 + ch * 8);
    }
    issue(0, 0); CP_COMMIT();
    issue(1, 1); CP_COMMIT();

    CP_WAIT(1);
    __syncthreads();

    // Q fragments -> registers
    uint32_t q[4][4];
#pragma unroll
    for (int kc = 0; kc < 4; kc++)
        ldsm4(q[kc], sQ + (w * 16 + arow) * AST + kc * 16 + acol);

    float o[8][4] = {};
    float l0 = 0.f, l1 = 0.f;

    for (int kt = 0; kt < NT; kt++) {
        int buf = kt & 1;
        if (kt) { CP_WAIT(1); __syncthreads(); }

        const __half* k0p = sK + buf * 64 * AST;
        const __half* v0p = sV + buf * 64 * AST;

        // S = Q K^T
        float s[8][4] = {};
#pragma unroll
        for (int nc = 0; nc < 4; nc++) {
#pragma unroll
            for (int kc = 0; kc < 4; kc++) {
                uint32_t kb[4];
                ldsm4(kb, k0p + (nc * 16 + brow) * AST + kc * 16 + bcol);
                mma_f16(s[nc*2],   q[kc], kb);
                mma_f16(s[nc*2+1], q[kc], kb + 2);
            }
        }

        // exp, row-sum, pack P as fp16 A-frags (C-frag == A-frag identity)
        uint32_t p[4][4];
#pragma unroll
        for (int t = 0; t < 8; t++) {
            float e0 = __expf(s[t][0] * scale), e1 = __expf(s[t][1] * scale);
            float e2 = __expf(s[t][2] * scale), e3 = __expf(s[t][3] * scale);
            l0 += e0 + e1;  l1 += e2 + e3;
            int kc = t >> 1, hf = t & 1;
            __half2 p01 = __floats2half2_rn(e0, e1);
            __half2 p23 = __floats2half2_rn(e2, e3);
            p[kc][hf*2]   = *(uint32_t*)&p01;
            p[kc][hf*2+1] = *(uint32_t*)&p23;
        }

        // O += P V
#pragma unroll
        for (int nd = 0; nd < 4; nd++) {
#pragma unroll
            for (int kc = 0; kc < 4; kc++) {
                uint32_t vb[4];
                ldsm4(vb, v0p + (nd * 16 + brow) * AST + kc * 16 + bcol);
                mma_f16(o[nd*2],   p[kc], vb);
                mma_f16(o[nd*2+1], p[kc], vb + 2);
            }
        }

        __syncthreads();
        if (kt + 2 < NT) issue(kt + 2, buf);
        CP_COMMIT();
    }
    CP_WAIT(0);

    // finalize row sums + write ctx hi/lo bf16
    l0 += __shfl_xor_sync(0xffffffffu, l0, 1);
    l0 += __shfl_xor_sync(0xffffffffu, l0, 2);
    l1 += __shfl_xor_sync(0xffffffffu, l1, 1);
    l1 += __shfl_xor_sync(0xffffffffu, l1, 2);
    float inv0 = 1.f / l0, inv1 = 1.f / l1;

    int r0 = q0 + w * 16 + (lane >> 2);
#pragma unroll
    for (int t = 0; t < 8; t++) {
        int c = h * 64 + t * 8 + 2 * (lane & 3);
        size_t g0 = ((size_t)b * SS + r0) * EE + c;
        size_t g1 = ((size_t)b * SS + r0 + 8) * EE + c;
        float v00 = o[t][0] * inv0, v01 = o[t][1] * inv0;
        float v10 = o[t][2] * inv1, v11 = o[t][3] * inv1;
        bf162 h2 = __floats2bfloat162_rn(v00, v01), L2;
        L2.x = __float2bfloat16(v00 - __bfloat162float(h2.x));
        L2.y = __float2bfloat16(v01 - __bfloat162float(h2.y));
        *(bf162*)&Ch_[g0] = h2; *(bf162*)&Cl_[g0] = L2;
        h2 = __floats2bfloat162_rn(v10, v11);
        L2.x = __float2bfloat16(v10 - __bfloat162float(h2.x));
        L2.y = __float2bfloat16(v11 - __bfloat162float(h2.y));
        *(bf162*)&Ch_[g1] = h2; *(bf162*)&Cl_[g1] = L2;
    }
}

// Penalty = 0.01 * sum(sigmoid(z))
__global__ void penalty_kernel(const float* __restrict__ z,
                               float* __restrict__ out, int out_size)
{
    if (out_size <= OUT_ELEMS) return;
    float v = 0.f;
    if (threadIdx.x < HH) v = 1.f / (1.f + expf(-z[threadIdx.x]));
#pragma unroll
    for (int off = 16; off > 0; off >>= 1)
        v += __shfl_xor_sync(0xffffffffu, v, off);
    if (threadIdx.x == 0) out[OUT_ELEMS] = v * 0.01f;
}

extern "C" void kernel_launch(void* const* d_in, const int* in_sizes, int n_in,
                              void* d_out, int out_size)
{
    const float* x  = (const float*)d_in[0];
    const float* Wq = (const float*)d_in[1];
    const float* bq = (const float*)d_in[2];
    const float* Wk = (const float*)d_in[3];
    const float* bk = (const float*)d_in[4];
    const float* Wv = (const float*)d_in[5];
    const float* bv = (const float*)d_in[6];
    const float* Wo = (const float*)d_in[7];
    const float* bo = (const float*)d_in[8];
    const float* z  = (const float*)d_in[9];
    float* out = (float*)d_out;

    bf16 *xh, *xl, *Wvh, *Wvl, *Woh, *Wol, *Ch, *Cl;
    __half *x16, *Wq16, *Wk16, *Q16, *K16, *Vt;
    cudaGetSymbolAddress((void**)&xh, g_xh);     cudaGetSymbolAddress((void**)&xl, g_xl);
    cudaGetSymbolAddress((void**)&x16, g_x16);
    cudaGetSymbolAddress((void**)&Wq16, g_Wq16); cudaGetSymbolAddress((void**)&Wk16, g_Wk16);
    cudaGetSymbolAddress((void**)&Wvh, g_Wvh);   cudaGetSymbolAddress((void**)&Wvl, g_Wvl);
    cudaGetSymbolAddress((void**)&Woh, g_Woh);   cudaGetSymbolAddress((void**)&Wol, g_Wol);
    cudaGetSymbolAddress((void**)&Q16, g_Q16);   cudaGetSymbolAddress((void**)&K16, g_K16);
    cudaGetSymbolAddress((void**)&Vt, g_Vt);
    cudaGetSymbolAddress((void**)&Ch, g_Ch);     cudaGetSymbolAddress((void**)&Cl, g_Cl);

    // prep
    split_x_kernel<<<(MM*EE/4 + 255)/256, 256>>>(x, xh, xl, x16, MM*EE/4);
    cvt16_kernel<<<(EE*EE/4 + 255)/256, 256>>>(Wq, Wq16, EE*EE/4);
    cvt16_kernel<<<(EE*EE/4 + 255)/256, 256>>>(Wk, Wk16, EE*EE/4);
    split_kernel<<<(EE*EE/4 + 255)/256, 256>>>(Wv, Wvh, Wvl, EE*EE/4);
    split_kernel<<<(EE*EE/4 + 255)/256, 256>>>(Wo, Woh, Wol, EE*EE/4);

    dim3 ggrid(EE / 128, MM / 128);       // (8, 32)

    const int FSM = 2 * 2 * 5120 * 2;     // 40960 B
    cudaFuncSetAttribute(gemm_f16, cudaFuncAttributeMaxDynamicSharedMemorySize, FSM);
    gemm_f16<<<ggrid, 256, FSM>>>(x16, Wq16, bq, Q16);
    gemm_f16<<<ggrid, 256, FSM>>>(x16, Wk16, bk, K16);

    const int GSM = 2 * 4 * 5120 * 2;     // 81920 B
    cudaFuncSetAttribute(gemm3<1>, cudaFuncAttributeMaxDynamicSharedMemorySize, GSM);
    cudaFuncSetAttribute(gemm3<2>, cudaFuncAttributeMaxDynamicSharedMemorySize, GSM);
    gemm3<1><<<ggrid, 256, GSM>>>(xh, xl, Wvh, Wvl, bv, Vt);

    const int ASM = 5 * 64 * AST * 2;     // 46080 B
    cudaFuncSetAttribute(attn_pipe, cudaFuncAttributeMaxDynamicSharedMemorySize, ASM);
    dim3 agrid(SS / 64, HH, BB);          // (32, 16, 2)
    attn_pipe<<<agrid, 128, ASM>>>(Q16, K16, Vt, z, Ch, Cl);

    gemm3<2><<<ggrid, 256, GSM>>>(Ch, Cl, Woh, Wol, bo, out);

    penalty_kernel<<<1, 32>>>(z, out, out_size);
}

// round 8
// speedup vs baseline: 9.2798x; 1.5377x over previous
#include <cuda_runtime.h>
#include <cuda_fp16.h>
#include <cstdint>

#define BB 2
#define SS 2048
#define EE 1024
#define HH 16
#define MM (BB*SS)          // 4096
#define OUT_ELEMS (MM*EE)   // 4194304
#define NT (SS/64)          // 32 k-tiles

// ---------------- scratch (device globals, all fp16 now) ----------------
__device__ __half g_x16[(size_t)MM*EE];
__device__ __half g_Wq16[EE*EE], g_Wk16[EE*EE], g_Wv16[EE*EE], g_Wo16[EE*EE];
__device__ __half g_Q16[(size_t)MM*EE];   // [b,h,s,d], pre-scaled by gate*0.125*log2e
__device__ __half g_K16[(size_t)MM*EE];   // [b,h,s,d]
__device__ __half g_Vt [(size_t)MM*EE];   // [b,h,d,s]
__device__ __half g_C16[(size_t)MM*EE];   // ctx [b,s,e]

// ---------------- asm helpers ----------------
__device__ __forceinline__ void mma_f16(float (&d)[4], const uint32_t (&a)[4],
                                        const uint32_t* b) {
    asm volatile(
        "mma.sync.aligned.m16n8k16.row.col.f32.f16.f16.f32 "
        "{%0,%1,%2,%3}, {%4,%5,%6,%7}, {%8,%9}, {%0,%1,%2,%3};\n"
        : "+f"(d[0]), "+f"(d[1]), "+f"(d[2]), "+f"(d[3])
        : "r"(a[0]), "r"(a[1]), "r"(a[2]), "r"(a[3]), "r"(b[0]), "r"(b[1]));
}
__device__ __forceinline__ void ldsm4(uint32_t (&r)[4], const void* p) {
    uint32_t a = (uint32_t)__cvta_generic_to_shared(p);
    asm volatile("ldmatrix.sync.aligned.m8n8.x4.shared.b16 {%0,%1,%2,%3}, [%4];\n"
                 : "=r"(r[0]), "=r"(r[1]), "=r"(r[2]), "=r"(r[3]) : "r"(a));
}
__device__ __forceinline__ void cpa16(void* d, const void* s) {
    uint32_t a = (uint32_t)__cvta_generic_to_shared(d);
    asm volatile("cp.async.cg.shared.global [%0], [%1], 16;\n" :: "r"(a), "l"(s));
}
__device__ __forceinline__ float ex2(float x) {
    float r;
    asm("ex2.approx.ftz.f32 %0, %1;" : "=f"(r) : "f"(x));
    return r;
}
#define CP_COMMIT() asm volatile("cp.async.commit_group;\n")
#define CP_WAIT(N)  asm volatile("cp.async.wait_group %0;\n" :: "n"(N))

// ---------------- prep: fp32 -> fp16 ----------------
__global__ void cvt_x(const float* __restrict__ in, __half* __restrict__ o, int n4) {
    int i = blockIdx.x * blockDim.x + threadIdx.x;
    if (i >= n4) return;
    float4 v = ((const float4*)in)[i];
    ((__half2*)o)[i*2]   = __floats2half2_rn(v.x, v.y);
    ((__half2*)o)[i*2+1] = __floats2half2_rn(v.z, v.w);
}
__global__ void cvt_w4(const float* __restrict__ s0, const float* __restrict__ s1,
                       const float* __restrict__ s2, const float* __restrict__ s3,
                       __half* __restrict__ d0, __half* __restrict__ d1,
                       __half* __restrict__ d2, __half* __restrict__ d3, int n4) {
    int i = blockIdx.x * blockDim.x + threadIdx.x;
    if (i >= n4) return;
    const float* s = (blockIdx.y == 0) ? s0 : (blockIdx.y == 1) ? s1 :
                     (blockIdx.y == 2) ? s2 : s3;
    __half* d = (blockIdx.y == 0) ? d0 : (blockIdx.y == 1) ? d1 :
                (blockIdx.y == 2) ? d2 : d3;
    float4 v = ((const float4*)s)[i];
    ((__half2*)d)[i*2]   = __floats2half2_rn(v.x, v.y);
    ((__half2*)d)[i*2+1] = __floats2half2_rn(v.z, v.w);
}

#define GST 40   // smem row stride (halves): 32 + 8 pad

// ---------------------------------------------------------------------------
// fp16 GEMM: C = A @ W^T + bias, BM=128 BN=128 BK=32, 256 thr, 2-stage.
//   MODE 0: -> fp16 [b,h,s,d], scaled by gate(h)*0.125*log2e  (Q)
//   MODE 1: -> fp16 [b,h,s,d]                                 (K)
//   MODE 2: -> fp16 [b,h,d,s] transposed                      (V)
//   MODE 3: -> fp32 [m,n]                                     (out)
// ---------------------------------------------------------------------------
template<int MODE>
__global__ __launch_bounds__(256, 2) void gemm_f16(
    const __half* __restrict__ A, const __half* __restrict__ B,
    const float* __restrict__ bias, const float* __restrict__ z,
    void* __restrict__ O)
{
    extern __shared__ __half smh[];   // 2 stages x 2 arrays x 5120 halves

    const int tid = threadIdx.x, lane = tid & 31, wid = tid >> 5;
    const int wm = wid & 3, wn = wid >> 2;
    const int m0 = blockIdx.y * 128, n0 = blockIdx.x * 128;
    const int arow = (lane & 7) + ((lane >> 3) & 1) * 8, acol = ((lane >> 4) & 1) * 8;
    const int brow = (lane & 7) + ((lane >> 4) & 1) * 8, bcol = ((lane >> 3) & 1) * 8;

    auto issue = [&](int k0, int buf) {
        __half* base = smh + buf * 2 * 5120;
#pragma unroll
        for (int i = 0; i < 4; i++) {
            int idx = tid + i * 256;          // 0..1023
            int isB = idx >= 512;
            int rem = idx & 511;
            int row = rem >> 2, ch = rem & 3;
            const __half* src = (isB ? B + (size_t)(n0 + row) * EE
                                     : A + (size_t)(m0 + row) * EE) + k0 + ch * 8;
            cpa16(base + isB * 5120 + row * GST + ch * 8, src);
        }
    };

    float acc[2][8][4] = {};
    issue(0, 0);  CP_COMMIT();
    issue(32, 1); CP_COMMIT();

    for (int s = 0; s < EE / 32; s++) {
        CP_WAIT(1);
        __syncthreads();
        __half* sA = smh + (s & 1) * 2 * 5120;
        __half* sB = sA + 5120;

#pragma unroll
        for (int ks = 0; ks < 32; ks += 16) {
            uint32_t a[2][4];
#pragma unroll
            for (int mt = 0; mt < 2; mt++)
                ldsm4(a[mt], sA + (wm * 32 + mt * 16 + arow) * GST + ks + acol);
#pragma unroll
            for (int np = 0; np < 4; np++) {
                uint32_t bf[4];
                ldsm4(bf, sB + (wn * 64 + np * 16 + brow) * GST + ks + bcol);
#pragma unroll
                for (int mt = 0; mt < 2; mt++) {
                    mma_f16(acc[mt][np*2],   a[mt], bf);
                    mma_f16(acc[mt][np*2+1], a[mt], bf + 2);
                }
            }
        }
        __syncthreads();
        if (s + 2 < EE / 32) issue((s + 2) * 32, s & 1);
        CP_COMMIT();
    }
    CP_WAIT(0);

#pragma unroll
    for (int mt = 0; mt < 2; mt++) {
        int r = m0 + wm * 32 + mt * 16 + (lane >> 2);
#pragma unroll
        for (int nt = 0; nt < 8; nt++) {
            int c = n0 + wn * 64 + nt * 8 + 2 * (lane & 3);
            float b0 = bias[c], b1 = bias[c + 1];
            float v00 = acc[mt][nt][0] + b0, v01 = acc[mt][nt][1] + b1;
            float v10 = acc[mt][nt][2] + b0, v11 = acc[mt][nt][3] + b1;
            if (MODE == 3) {
                float* Of = (float*)O;
                *(float2*)&Of[(size_t)r * EE + c]       = make_float2(v00, v01);
                *(float2*)&Of[(size_t)(r + 8) * EE + c] = make_float2(v10, v11);
            } else {
                int b_ = r >> 11, s_ = r & 2047, hh = c >> 6, dd = c & 63;
                __half* Oh = (__half*)O;
                if (MODE == 2) {   // V transposed [b,h,d,s]
                    size_t o0 = (((size_t)b_ * HH + hh) * 64 + dd) * SS + s_;
                    Oh[o0]          = __float2half(v00);
                    Oh[o0 + SS]     = __float2half(v01);
                    Oh[o0 + 8]      = __float2half(v10);
                    Oh[o0 + SS + 8] = __float2half(v11);
                } else {           // Q/K [b,h,s,d]
                    if (MODE == 0) {
                        float mult = 0.18033688f / (1.f + __expf(-z[hh]));
                        v00 *= mult; v01 *= mult; v10 *= mult; v11 *= mult;
                    }
                    size_t o0 = (((size_t)b_ * HH + hh) * SS + s_) * 64 + dd;
                    *(__half2*)&Oh[o0] = __floats2half2_rn(v00, v01);
                    *(__half2*)&Oh[o0 + (size_t)8 * 64] = __floats2half2_rn(v10, v11);
                }
            }
        }
    }
}

// ---------------------------------------------------------------------------
// Attention: fp16 throughout. Per (b,h,64-query tile), 128 thr (4 warps).
// Q pre-scaled so p = 2^s. Row sums via ones-column MMA (no shuffles).
// smem fp16 (stride 72): Q[64], K[2][64], V[2][64] = 46080 B.
// ---------------------------------------------------------------------------
#define AST 72

__global__ __launch_bounds__(128, 4) void attn_pipe(
    const __half* __restrict__ Q16, const __half* __restrict__ K16,
    const __half* __restrict__ Vt_, __half* __restrict__ C16)
{
    extern __shared__ __half smf[];
    __half* sQ = smf;                       // 64*72
    __half* sK = sQ + 64 * AST;             // 2 x 64*72
    __half* sV = sK + 2 * 64 * AST;         // 2 x 64*72

    const int tid = threadIdx.x, lane = tid & 31, w = tid >> 5;
    const int q0 = blockIdx.x * 64, h = blockIdx.y, b = blockIdx.z;
    const int bh = b * HH + h;

    const size_t qkBase = (size_t)bh * SS * 64;   // [bh][s][d]
    const size_t vBase  = (size_t)bh * 64 * SS;   // [bh][d][s]

    const int arow = (lane & 7) + ((lane >> 3) & 1) * 8, acol = ((lane >> 4) & 1) * 8;
    const int brow = (lane & 7) + ((lane >> 4) & 1) * 8, bcol = ((lane >> 3) & 1) * 8;

    auto issue = [&](int kt, int buf) {
#pragma unroll
        for (int i = 0; i < 8; i++) {
            int idx = tid + i * 128;           // 0..1023
            if (idx < 512) {                   // K tile
                int row = idx >> 3, ch = idx & 7;
                cpa16(sK + buf * 64 * AST + row * AST + ch * 8,
                      K16 + qkBase + (size_t)(kt * 64 + row) * 64 + ch * 8);
            } else {                           // V tile
                int rem = idx - 512, row = rem >> 3, ch = rem & 7;
                cpa16(sV + buf * 64 * AST + row * AST + ch * 8,
                      Vt_ + vBase + (size_t)row * SS + kt * 64 + ch * 8);
            }
        }
    };

#pragma unroll
    for (int i = 0; i < 4; i++) {
        int idx = tid + i * 128;               // 0..511
        int row = idx >> 3, ch = idx & 7;
        cpa16(sQ + row * AST + ch * 8,
              Q16 + qkBase + (size_t)(q0 + row) * 64 + ch * 8);
    }
    issue(0, 0); CP_COMMIT();
    issue(1, 1); CP_COMMIT();

    CP_WAIT(1);
    __syncthreads();

    uint32_t q[4][4];
#pragma unroll
    for (int kc = 0; kc < 4; kc++)
        ldsm4(q[kc], sQ + (w * 16 + arow) * AST + kc * 16 + acol);

    float o[8][4] = {};
    float ol[4] = {};                       // row-sum accumulator (ones column)
    const uint32_t ONE2 = 0x3C003C00u;      // half2(1,1)
    const uint32_t ones[2] = {ONE2, ONE2};

    for (int kt = 0; kt < NT; kt++) {
        int buf = kt & 1;
        if (kt) { CP_WAIT(1); __syncthreads(); }

        const __half* k0p = sK + buf * 64 * AST;
        const __half* v0p = sV + buf * 64 * AST;

        // S = Q K^T (already log2-scaled)
        float s[8][4] = {};
#pragma unroll
        for (int nc = 0; nc < 4; nc++) {
#pragma unroll
            for (int kc = 0; kc < 4; kc++) {
                uint32_t kb[4];
                ldsm4(kb, k0p + (nc * 16 + brow) * AST + kc * 16 + bcol);
                mma_f16(s[nc*2],   q[kc], kb);
                mma_f16(s[nc*2+1], q[kc], kb + 2);
            }
        }

        // p = 2^s, packed fp16 A-frags (C-frag == A-frag identity)
        uint32_t p[4][4];
#pragma unroll
        for (int t = 0; t < 8; t++) {
            float e0 = ex2(s[t][0]), e1 = ex2(s[t][1]);
            float e2 = ex2(s[t][2]), e3 = ex2(s[t][3]);
            int kc = t >> 1, hf = t & 1;
            __half2 p01 = __floats2half2_rn(e0, e1);
            __half2 p23 = __floats2half2_rn(e2, e3);
            p[kc][hf*2]   = *(uint32_t*)&p01;
            p[kc][hf*2+1] = *(uint32_t*)&p23;
        }

        // O += P V ; row sums += P @ ones
#pragma unroll
        for (int kc = 0; kc < 4; kc++) {
#pragma unroll
            for (int nd = 0; nd < 4; nd++) {
                uint32_t vb[4];
                ldsm4(vb, v0p + (nd * 16 + brow) * AST + kc * 16 + bcol);
                mma_f16(o[nd*2],   p[kc], vb);
                mma_f16(o[nd*2+1], p[kc], vb + 2);
            }
            mma_f16(ol, p[kc], ones);
        }

        __syncthreads();
        if (kt + 2 < NT) issue(kt + 2, buf);
        CP_COMMIT();
    }
    CP_WAIT(0);

    float inv0 = 1.f / ol[0], inv1 = 1.f / ol[2];

    int r0 = q0 + w * 16 + (lane >> 2);
#pragma unroll
    for (int t = 0; t < 8; t++) {
        int c = h * 64 + t * 8 + 2 * (lane & 3);
        size_t g0 = ((size_t)b * SS + r0) * EE + c;
        size_t g1 = ((size_t)b * SS + r0 + 8) * EE + c;
        *(__half2*)&C16[g0] = __floats2half2_rn(o[t][0] * inv0, o[t][1] * inv0);
        *(__half2*)&C16[g1] = __floats2half2_rn(o[t][2] * inv1, o[t][3] * inv1);
    }
}

// Penalty = 0.01 * sum(sigmoid(z))
__global__ void penalty_kernel(const float* __restrict__ z,
                               float* __restrict__ out, int out_size)
{
    if (out_size <= OUT_ELEMS) return;
    float v = 0.f;
    if (threadIdx.x < HH) v = 1.f / (1.f + expf(-z[threadIdx.x]));
#pragma unroll
    for (int off = 16; off > 0; off >>= 1)
        v += __shfl_xor_sync(0xffffffffu, v, off);
    if (threadIdx.x == 0) out[OUT_ELEMS] = v * 0.01f;
}

extern "C" void kernel_launch(void* const* d_in, const int* in_sizes, int n_in,
                              void* d_out, int out_size)
{
    const float* x  = (const float*)d_in[0];
    const float* Wq = (const float*)d_in[1];
    const float* bq = (const float*)d_in[2];
    const float* Wk = (const float*)d_in[3];
    const float* bk = (const float*)d_in[4];
    const float* Wv = (const float*)d_in[5];
    const float* bv = (const float*)d_in[6];
    const float* Wo = (const float*)d_in[7];
    const float* bo = (const float*)d_in[8];
    const float* z  = (const float*)d_in[9];
    float* out = (float*)d_out;

    __half *x16, *Wq16, *Wk16, *Wv16, *Wo16, *Q16, *K16, *Vt, *C16;
    cudaGetSymbolAddress((void**)&x16, g_x16);
    cudaGetSymbolAddress((void**)&Wq16, g_Wq16);
    cudaGetSymbolAddress((void**)&Wk16, g_Wk16);
    cudaGetSymbolAddress((void**)&Wv16, g_Wv16);
    cudaGetSymbolAddress((void**)&Wo16, g_Wo16);
    cudaGetSymbolAddress((void**)&Q16, g_Q16);
    cudaGetSymbolAddress((void**)&K16, g_K16);
    cudaGetSymbolAddress((void**)&Vt, g_Vt);
    cudaGetSymbolAddress((void**)&C16, g_C16);

    // prep (2 launches so ncu -s 5 lands on attn)
    cvt_x<<<(MM*EE/4 + 255)/256, 256>>>(x, x16, MM*EE/4);
    dim3 wgrid((EE*EE/4 + 255)/256, 4);
    cvt_w4<<<wgrid, 256>>>(Wq, Wk, Wv, Wo, Wq16, Wk16, Wv16, Wo16, EE*EE/4);

    dim3 ggrid(EE / 128, MM / 128);       // (8, 32)
    const int FSM = 2 * 2 * 5120 * 2;     // 40960 B
    cudaFuncSetAttribute(gemm_f16<0>, cudaFuncAttributeMaxDynamicSharedMemorySize, FSM);
    cudaFuncSetAttribute(gemm_f16<1>, cudaFuncAttributeMaxDynamicSharedMemorySize, FSM);
    cudaFuncSetAttribute(gemm_f16<2>, cudaFuncAttributeMaxDynamicSharedMemorySize, FSM);
    cudaFuncSetAttribute(gemm_f16<3>, cudaFuncAttributeMaxDynamicSharedMemorySize, FSM);

    gemm_f16<0><<<ggrid, 256, FSM>>>(x16, Wq16, bq, z, Q16);
    gemm_f16<1><<<ggrid, 256, FSM>>>(x16, Wk16, bk, nullptr, K16);
    gemm_f16<2><<<ggrid, 256, FSM>>>(x16, Wv16, bv, nullptr, Vt);

    const int ASM = 5 * 64 * AST * 2;     // 46080 B
    cudaFuncSetAttribute(attn_pipe, cudaFuncAttributeMaxDynamicSharedMemorySize, ASM);
    dim3 agrid(SS / 64, HH, BB);          // (32, 16, 2)
    attn_pipe<<<agrid, 128, ASM>>>(Q16, K16, Vt, C16);

    gemm_f16<3><<<ggrid, 256, FSM>>>(C16, Wo16, bo, nullptr, out);

    penalty_kernel<<<1, 32>>>(z, out, out_size);
}